// round 1
// baseline (speedup 1.0000x reference)
#include <cuda_runtime.h>

// Problem constants (fixed by the reference)
#define B_   1024
#define S_   336
#define C_   64
#define O_   168
#define T_   96
#define BT   64      // batch tile per block
#define XPITCH 169   // 168 + 1 pad -> tb*9 mod 32 spans 16 distinct banks

#define SMEM_FLOATS (BT * XPITCH + O_ * T_)
#define SMEM_BYTES  (SMEM_FLOATS * 4)

// Per block: one channel c, one 64-batch tile.
//   Y[b, t, c] = sum_o x[b, S-O+o, c] * W[c, o, t] + bias[c, t]
// 256 threads, each computes a 4(b) x 6(t) register tile, interleaved:
//   b = b0 + tb + i*16   (tb = tid % 16, i < 4)
//   t = tt + j*16        (tt = tid / 16, j < 6)
__global__ __launch_bounds__(256, 2)
void tcilr_kernel(const float* __restrict__ x,
                  const float* __restrict__ W,
                  const float* __restrict__ bias,
                  float* __restrict__ out)
{
    extern __shared__ float smem[];
    float* Xs = smem;                 // [BT][XPITCH]
    float* Ws = smem + BT * XPITCH;   // [O_][T_] contiguous

    const int c   = blockIdx.x;
    const int b0  = blockIdx.y * BT;
    const int tid = threadIdx.x;

    // ---- load W[c] : 168*96 = 16128 floats, fully coalesced ----
    const float* Wc = W + (size_t)c * (O_ * T_);
    #pragma unroll 4
    for (int i = tid; i < O_ * T_; i += 256)
        Ws[i] = Wc[i];

    // ---- load X tail: Xs[bb][o] = x[(b0+bb)*S*C + (S-O+o)*C + c] ----
    // (strided by 256B; relies on L2 dedup across the 64 concurrent
    //  channel-blocks of the same batch tile — grid.x is channel-fastest)
    const float* xc = x + (size_t)(S_ - O_) * C_ + c;
    #pragma unroll 2
    for (int i = tid; i < BT * O_; i += 256) {
        int bb = i / O_;
        int o  = i - bb * O_;
        Xs[bb * XPITCH + o] =
            xc[(size_t)(b0 + bb) * (S_ * C_) + (size_t)o * C_];
    }
    __syncthreads();

    const int tb = tid & 15;
    const int tt = tid >> 4;

    float acc[4][6];
    #pragma unroll
    for (int i = 0; i < 4; i++)
        #pragma unroll
        for (int j = 0; j < 6; j++)
            acc[i][j] = 0.0f;

    // ---- main K loop: 24 FFMA + 10 conflict-free LDS per k ----
    #pragma unroll 4
    for (int k = 0; k < O_; k++) {
        float a[4], w[6];
        #pragma unroll
        for (int i = 0; i < 4; i++)
            a[i] = Xs[(tb + i * 16) * XPITCH + k];
        #pragma unroll
        for (int j = 0; j < 6; j++)
            w[j] = Ws[k * T_ + tt + j * 16];
        #pragma unroll
        for (int i = 0; i < 4; i++)
            #pragma unroll
            for (int j = 0; j < 6; j++)
                acc[i][j] = fmaf(a[i], w[j], acc[i][j]);
    }

    // ---- epilogue: add bias, store out[b, t, c] ----
    #pragma unroll
    for (int j = 0; j < 6; j++) {
        const int t  = tt + j * 16;
        const float bv = bias[c * T_ + t];
        #pragma unroll
        for (int i = 0; i < 4; i++) {
            const int b = b0 + tb + i * 16;
            out[((size_t)b * T_ + t) * C_ + c] = acc[i][j] + bv;
        }
    }
}

extern "C" void kernel_launch(void* const* d_in, const int* in_sizes, int n_in,
                              void* d_out, int out_size)
{
    const float* x    = (const float*)d_in[0];  // [B, S, C] fp32
    const float* W    = (const float*)d_in[1];  // [C, O, T] fp32
    const float* bias = (const float*)d_in[2];  // [C, T]    fp32
    // d_in[3] = training flag (unused)
    float* out = (float*)d_out;                 // [B, T, C] fp32

    cudaFuncSetAttribute(tcilr_kernel,
                         cudaFuncAttributeMaxDynamicSharedMemorySize,
                         SMEM_BYTES);

    dim3 grid(C_, B_ / BT);   // channel-fastest for L2 sector dedup on x
    tcilr_kernel<<<grid, 256, SMEM_BYTES>>>(x, W, bias, out);
}